// round 8
// baseline (speedup 1.0000x reference)
#include <cuda_runtime.h>
#include <cuda_bf16.h>
#include <math_constants.h>

// GeomAttention: B=2, L=S=2048, H=8, E=D=32, fp32.
// Cauchy-Schwarz => relu never fires: score = c*(dot+dot^2) - c*qn2*kn2.
// Shift softmax: C = min(c*qn2*KMIN, 70) is a safe fixed shift (no online max).
//
// R8: 2 rows/thread (LDS amortized, balances fma/L1 pipes), chunk-4 scoring for
// ILP, kn2 precomputed by the pre-kernel (no per-tile kn2 pass), SPLITS=4 with
// launch_bounds(64,6) -> ~12 warps/SM, fused last-block merge.

static constexpr int B_ = 2, L_ = 2048, H_ = 8, E_ = 32;
static constexpr int SPLITS = 4;
static constexpr int SKEYS  = L_ / SPLITS;   // 512
static constexpr int TS = 64;                // keys per SMEM tile
static constexpr int CH = 4;                 // keys per score chunk
static constexpr int THREADS = 64;           // 2 warps
static constexpr int ROWSPB = 2 * THREADS;   // 128 rows per block
static constexpr int NR = B_ * L_ * H_;      // 32768 rows
static constexpr int NGROUPS = (L_ / ROWSPB) * H_ * B_;  // 256

__device__ float  g_l[SPLITS * NR];
__device__ float4 g_acc[SPLITS * NR * 8];
__device__ float  g_kmin[B_ * H_];
__device__ float  g_kn2[B_ * H_ * L_];       // [(b*H+h)*L + s]
__device__ int    g_cnt[NGROUPS];            // zero-init; self-resetting

typedef unsigned long long u64;

__device__ __forceinline__ u64 pk2(float a, float b) {
    u64 r; asm("mov.b64 %0, {%1,%2};" : "=l"(r) : "f"(a), "f"(b)); return r;
}
__device__ __forceinline__ float2 upk2(u64 v) {
    float2 r; asm("mov.b64 {%0,%1}, %2;" : "=f"(r.x), "=f"(r.y) : "l"(v)); return r;
}
__device__ __forceinline__ u64 ffma2(u64 a, u64 b, u64 c) {
    u64 d; asm("fma.rn.f32x2 %0, %1, %2, %3;" : "=l"(d) : "l"(a), "l"(b), "l"(c)); return d;
}

// ---- pre-kernel: per-key |k|^2 and per-(b,h) min ----
__global__ __launch_bounds__(256) void kprep_kernel(const float* __restrict__ K)
{
    const int bh = blockIdx.x;               // 0..B*H-1
    const int b = bh / H_, h = bh % H_;
    const float* kbase = K + (((size_t)b * L_) * H_ + h) * E_;
    float mn = CUDART_INF_F;
    for (int s = threadIdx.x; s < L_; s += 256) {
        const float4* kp = (const float4*)(kbase + (size_t)s * (H_ * E_));
        float kn = 0.f;
        #pragma unroll
        for (int j = 0; j < 8; j++) {
            float4 v = kp[j];
            kn += v.x*v.x + v.y*v.y + v.z*v.z + v.w*v.w;
        }
        g_kn2[(size_t)bh * L_ + s] = kn;
        mn = fminf(mn, kn);
    }
    #pragma unroll
    for (int o = 16; o; o >>= 1) mn = fminf(mn, __shfl_xor_sync(0xffffffffu, mn, o));
    __shared__ float red[8];
    if ((threadIdx.x & 31) == 0) red[threadIdx.x >> 5] = mn;
    __syncthreads();
    if (threadIdx.x == 0) {
        float r = red[0];
        #pragma unroll
        for (int w = 1; w < 8; w++) r = fminf(r, red[w]);
        g_kmin[bh] = r;
    }
}

__global__ __launch_bounds__(THREADS, 6) void geom_attn_fused(
    const float* __restrict__ Q, const float* __restrict__ K,
    const float* __restrict__ V, float* __restrict__ O)
{
    __shared__ float4 sK[TS * 8];
    __shared__ float4 sV[TS * 8];
    __shared__ float  sKn2[TS];
    __shared__ int    sLast;

    const int tid   = threadIdx.x;
    const int h     = blockIdx.y;
    const int bz    = blockIdx.z;
    const int b     = bz >> 2;                 // SPLITS == 4
    const int split = bz & 3;
    const int lbase = blockIdx.x * ROWSPB;
    const int l0    = lbase + tid;
    const int l1    = l0 + THREADS;
    const int bh    = b * H_ + h;

    // ---- load 2 query rows; |q|^2 each ----
    const float* qp0 = Q + (((size_t)b * L_ + l0) * H_ + h) * E_;
    const float* qp1 = Q + (((size_t)b * L_ + l1) * H_ + h) * E_;
    u64 qa[16], qb[16];
    float qn2a = 0.f, qn2b = 0.f;
    #pragma unroll
    for (int j = 0; j < 8; j++) {
        float4 t = ((const float4*)qp0)[j];
        qa[2*j] = pk2(t.x, t.y); qa[2*j+1] = pk2(t.z, t.w);
        qn2a += t.x*t.x + t.y*t.y + t.z*t.z + t.w*t.w;
        float4 u = ((const float4*)qp1)[j];
        qb[2*j] = pk2(u.x, u.y); qb[2*j+1] = pk2(u.z, u.w);
        qn2b += u.x*u.x + u.y*u.y + u.z*u.z + u.w*u.w;
    }

    const float c   = 0.5f * rsqrtf((float)E_);
    const float cqa = c * qn2a, cqb = c * qn2b;
    const float km  = g_kmin[bh];
    const float Ca  = fminf(cqa * km, 70.f);   // safe fixed shift
    const float Cb  = fminf(cqb * km, 70.f);

    float ls0 = 0.f, ls1 = 0.f;
    u64 acca[16], accb[16];
    #pragma unroll
    for (int j = 0; j < 16; j++) { acca[j] = 0ull; accb[j] = 0ull; }

    const int key0 = split * SKEYS;
    const float* kbase = K + (((size_t)b * L_) * H_ + h) * E_;
    const float* vbase = V + (((size_t)b * L_) * H_ + h) * E_;
    const float* knbase = &g_kn2[(size_t)bh * L_ + key0];

    for (int s0 = 0; s0 < SKEYS; s0 += TS) {
        #pragma unroll
        for (int i = tid; i < TS * 8; i += THREADS) {
            int r = i >> 3, j = i & 7;
            size_t off = (size_t)(key0 + s0 + r) * (H_ * E_);
            sK[i] = ((const float4*)(kbase + off))[j];
            sV[i] = ((const float4*)(vbase + off))[j];
        }
        sKn2[tid] = knbase[s0 + tid];          // THREADS == TS
        __syncthreads();

        for (int c0 = 0; c0 < TS; c0 += CH) {
            float sa[CH], sb[CH];
            // ---- phase 1: scores for CH keys x 2 rows (4 ILP chains each) ----
            #pragma unroll
            for (int u = 0; u < CH; u++) {
                const ulonglong2* kp = (const ulonglong2*)&sK[(c0 + u) * 8];
                u64 a0 = 0ull, a1 = 0ull, b0 = 0ull, b1 = 0ull;
                #pragma unroll
                for (int j = 0; j < 8; j++) {
                    ulonglong2 kk = kp[j];          // broadcast across warp
                    a0 = ffma2(qa[2*j],   kk.x, a0);
                    a1 = ffma2(qa[2*j+1], kk.y, a1);
                    b0 = ffma2(qb[2*j],   kk.x, b0);
                    b1 = ffma2(qb[2*j+1], kk.y, b1);
                }
                float2 ra0 = upk2(a0), ra1 = upk2(a1);
                float2 rb0 = upk2(b0), rb1 = upk2(b1);
                float dota = (ra0.x + ra0.y) + (ra1.x + ra1.y);
                float dotb = (rb0.x + rb0.y) + (rb1.x + rb1.y);
                float kn2  = sKn2[c0 + u];
                float ta = fmaf(dota, dota, dota);   // dot + dot^2
                float tb = fmaf(dotb, dotb, dotb);
                sa[u] = fmaf(c, ta, fmaf(-cqa, kn2, Ca));
                sb[u] = fmaf(c, tb, fmaf(-cqb, kn2, Cb));
            }
            // ---- phase 2: exp + PV accumulate (straight-line) ----
            #pragma unroll
            for (int u = 0; u < CH; u++) {
                float pa = __expf(sa[u]);
                float pb = __expf(sb[u]);
                ls0 += pa; ls1 += pb;
                u64 ppa = pk2(pa, pa), ppb = pk2(pb, pb);
                const ulonglong2* vp = (const ulonglong2*)&sV[(c0 + u) * 8];
                #pragma unroll
                for (int j = 0; j < 8; j++) {
                    ulonglong2 vv = vp[j];
                    acca[2*j]   = ffma2(ppa, vv.x, acca[2*j]);
                    acca[2*j+1] = ffma2(ppa, vv.y, acca[2*j+1]);
                    accb[2*j]   = ffma2(ppb, vv.x, accb[2*j]);
                    accb[2*j+1] = ffma2(ppb, vv.y, accb[2*j+1]);
                }
            }
        }
        __syncthreads();
    }

    // ---- write partials ----
    const int r0 = ((b * L_ + l0) * H_ + h);
    const int r1 = ((b * L_ + l1) * H_ + h);
    g_l[split * NR + r0] = ls0;
    g_l[split * NR + r1] = ls1;
    float4* pa4 = &g_acc[(size_t)(split * NR + r0) * 8];
    float4* pb4 = &g_acc[(size_t)(split * NR + r1) * 8];
    #pragma unroll
    for (int j = 0; j < 8; j++) {
        float2 x = upk2(acca[2*j]), y = upk2(acca[2*j+1]);
        pa4[j] = make_float4(x.x, x.y, y.x, y.y);
        float2 u = upk2(accb[2*j]), v = upk2(accb[2*j+1]);
        pb4[j] = make_float4(u.x, u.y, v.x, v.y);
    }

    // ---- last block of this group merges the splits (plain sums) ----
    const int g = blockIdx.x + (L_ / ROWSPB) * (h + H_ * b);
    __threadfence();
    if (tid == 0) {
        int prev = atomicAdd(&g_cnt[g], 1);
        sLast = (prev == SPLITS - 1);
    }
    __syncthreads();
    if (!sLast) return;
    __threadfence();

    // 64 threads merge 128 rows x 8 float4 chunks = 1024 items.
    #pragma unroll 1
    for (int it = 0; it < (ROWSPB * 8) / THREADS; it++) {
        int item = it * THREADS + tid;
        int rl = item >> 3;
        int jj = item & 7;
        int r  = ((b * L_ + lbase + rl) * H_ + h);
        float denom = 0.f;
        float4 o = make_float4(0.f, 0.f, 0.f, 0.f);
        #pragma unroll
        for (int sp = 0; sp < SPLITS; sp++) {
            denom += g_l[sp * NR + r];
            float4 a = g_acc[(size_t)(sp * NR + r) * 8 + jj];
            o.x += a.x; o.y += a.y; o.z += a.z; o.w += a.w;
        }
        float inv = 1.0f / denom;
        o.x *= inv; o.y *= inv; o.z *= inv; o.w *= inv;
        ((float4*)O)[(size_t)r * 8 + jj] = o;
    }
    if (tid == 0) g_cnt[g] = 0;   // self-reset for next graph replay
}

extern "C" void kernel_launch(void* const* d_in, const int* in_sizes, int n_in,
                              void* d_out, int out_size) {
    const float* Q = (const float*)d_in[0];
    const float* K = (const float*)d_in[1];
    const float* V = (const float*)d_in[2];
    float* O = (float*)d_out;
    (void)in_sizes; (void)n_in; (void)out_size;
    kprep_kernel<<<B_ * H_, 256>>>(K);
    dim3 grid(L_ / ROWSPB, H_, B_ * SPLITS);   // 16 x 8 x 8 = 1024 blocks
    geom_attn_fused<<<grid, THREADS>>>(Q, K, V, O);
}

// round 9
// speedup vs baseline: 1.3722x; 1.3722x over previous
#include <cuda_runtime.h>
#include <cuda_bf16.h>
#include <math_constants.h>

// GeomAttention: B=2, L=S=2048, H=8, E=D=32, fp32.
// Cauchy-Schwarz => relu never fires: score = c*(dot+dot^2) - c*qn2*kn2.
// Shift softmax: C = min(c*qn2*KMIN, 70) is a safe fixed shift (no online max).
//
// R9: R3's exact fast structure (SPLITS=2, 2 rows/thread, chunk-8, uncapped
// regs) with the online-softmax machinery replaced by the shift softmax,
// kn2 precomputed (one fewer sync/tile), TS=128 (half the tile syncs).

static constexpr int B_ = 2, L_ = 2048, H_ = 8, E_ = 32;
static constexpr int SPLITS = 2;
static constexpr int SKEYS  = L_ / SPLITS;   // 1024
static constexpr int TS = 128;               // keys per SMEM tile
static constexpr int CH = 8;                 // keys per score chunk
static constexpr int THREADS = 64;           // 2 warps
static constexpr int ROWSPB = 2 * THREADS;   // 128 rows per block
static constexpr int NR = B_ * L_ * H_;      // 32768 rows
static constexpr int NGROUPS = (L_ / ROWSPB) * H_ * B_;  // 256

__device__ float  g_l[SPLITS * NR];
__device__ float4 g_acc[SPLITS * NR * 8];
__device__ float  g_kmin[B_ * H_];
__device__ float  g_kn2[B_ * H_ * L_];       // [(b*H+h)*L + s]
__device__ int    g_cnt[NGROUPS];            // zero-init; self-resetting

typedef unsigned long long u64;

__device__ __forceinline__ u64 pk2(float a, float b) {
    u64 r; asm("mov.b64 %0, {%1,%2};" : "=l"(r) : "f"(a), "f"(b)); return r;
}
__device__ __forceinline__ float2 upk2(u64 v) {
    float2 r; asm("mov.b64 {%0,%1}, %2;" : "=f"(r.x), "=f"(r.y) : "l"(v)); return r;
}
__device__ __forceinline__ u64 ffma2(u64 a, u64 b, u64 c) {
    u64 d; asm("fma.rn.f32x2 %0, %1, %2, %3;" : "=l"(d) : "l"(a), "l"(b), "l"(c)); return d;
}

// ---- pre-kernel: per-key |k|^2 and per-(b,h) min ----
__global__ __launch_bounds__(256) void kprep_kernel(const float* __restrict__ K)
{
    const int bh = blockIdx.x;               // 0..B*H-1
    const int b = bh / H_, h = bh % H_;
    const float* kbase = K + (((size_t)b * L_) * H_ + h) * E_;
    float mn = CUDART_INF_F;
    for (int s = threadIdx.x; s < L_; s += 256) {
        const float4* kp = (const float4*)(kbase + (size_t)s * (H_ * E_));
        float kn = 0.f;
        #pragma unroll
        for (int j = 0; j < 8; j++) {
            float4 v = kp[j];
            kn += v.x*v.x + v.y*v.y + v.z*v.z + v.w*v.w;
        }
        g_kn2[(size_t)bh * L_ + s] = kn;
        mn = fminf(mn, kn);
    }
    #pragma unroll
    for (int o = 16; o; o >>= 1) mn = fminf(mn, __shfl_xor_sync(0xffffffffu, mn, o));
    __shared__ float red[8];
    if ((threadIdx.x & 31) == 0) red[threadIdx.x >> 5] = mn;
    __syncthreads();
    if (threadIdx.x == 0) {
        float r = red[0];
        #pragma unroll
        for (int w = 1; w < 8; w++) r = fminf(r, red[w]);
        g_kmin[bh] = r;
    }
}

__global__ __launch_bounds__(THREADS, 4) void geom_attn_fused(
    const float* __restrict__ Q, const float* __restrict__ K,
    const float* __restrict__ V, float* __restrict__ O)
{
    __shared__ float4 sK[TS * 8];    // 16 KB
    __shared__ float4 sV[TS * 8];    // 16 KB
    __shared__ float  sKn2[TS];
    __shared__ int    sLast;

    const int tid   = threadIdx.x;
    const int h     = blockIdx.y;
    const int bz    = blockIdx.z;
    const int b     = bz >> 1;                 // SPLITS == 2
    const int split = bz & 1;
    const int lbase = blockIdx.x * ROWSPB;
    const int l0    = lbase + tid;
    const int l1    = l0 + THREADS;
    const int bh    = b * H_ + h;

    // ---- load 2 query rows; |q|^2 each ----
    const float* qp0 = Q + (((size_t)b * L_ + l0) * H_ + h) * E_;
    const float* qp1 = Q + (((size_t)b * L_ + l1) * H_ + h) * E_;
    u64 qa[16], qb[16];
    float qn2a = 0.f, qn2b = 0.f;
    #pragma unroll
    for (int j = 0; j < 8; j++) {
        float4 t = ((const float4*)qp0)[j];
        qa[2*j] = pk2(t.x, t.y); qa[2*j+1] = pk2(t.z, t.w);
        qn2a += t.x*t.x + t.y*t.y + t.z*t.z + t.w*t.w;
        float4 u = ((const float4*)qp1)[j];
        qb[2*j] = pk2(u.x, u.y); qb[2*j+1] = pk2(u.z, u.w);
        qn2b += u.x*u.x + u.y*u.y + u.z*u.z + u.w*u.w;
    }

    const float c   = 0.5f * rsqrtf((float)E_);
    const float cqa = c * qn2a, cqb = c * qn2b;
    const float km  = g_kmin[bh];
    const float Ca  = fminf(cqa * km, 70.f);   // safe fixed shift
    const float Cb  = fminf(cqb * km, 70.f);

    float ls0 = 0.f, ls1 = 0.f;
    u64 acca[16], accb[16];
    #pragma unroll
    for (int j = 0; j < 16; j++) { acca[j] = 0ull; accb[j] = 0ull; }

    const int key0 = split * SKEYS;
    const float* kbase = K + (((size_t)b * L_) * H_ + h) * E_;
    const float* vbase = V + (((size_t)b * L_) * H_ + h) * E_;
    const float* knbase = &g_kn2[(size_t)bh * L_ + key0];

    for (int s0 = 0; s0 < SKEYS; s0 += TS) {
        #pragma unroll
        for (int i = tid; i < TS * 8; i += THREADS) {
            int r = i >> 3, j = i & 7;
            size_t off = (size_t)(key0 + s0 + r) * (H_ * E_);
            sK[i] = ((const float4*)(kbase + off))[j];
            sV[i] = ((const float4*)(vbase + off))[j];
        }
        #pragma unroll
        for (int i = tid; i < TS; i += THREADS)
            sKn2[i] = knbase[s0 + i];
        __syncthreads();

        for (int c0 = 0; c0 < TS; c0 += CH) {
            float sa[CH], sb[CH];
            // ---- phase 1: scores for CH keys x 2 rows (4 ILP chains each) ----
            #pragma unroll
            for (int u = 0; u < CH; u++) {
                const ulonglong2* kp = (const ulonglong2*)&sK[(c0 + u) * 8];
                u64 a0 = 0ull, a1 = 0ull, b0 = 0ull, b1 = 0ull;
                #pragma unroll
                for (int j = 0; j < 8; j++) {
                    ulonglong2 kk = kp[j];          // broadcast across warp
                    a0 = ffma2(qa[2*j],   kk.x, a0);
                    a1 = ffma2(qa[2*j+1], kk.y, a1);
                    b0 = ffma2(qb[2*j],   kk.x, b0);
                    b1 = ffma2(qb[2*j+1], kk.y, b1);
                }
                float2 ra0 = upk2(a0), ra1 = upk2(a1);
                float2 rb0 = upk2(b0), rb1 = upk2(b1);
                float dota = (ra0.x + ra0.y) + (ra1.x + ra1.y);
                float dotb = (rb0.x + rb0.y) + (rb1.x + rb1.y);
                float kn2  = sKn2[c0 + u];
                float ta = fmaf(dota, dota, dota);   // dot + dot^2
                float tb = fmaf(dotb, dotb, dotb);
                sa[u] = fmaf(c, ta, fmaf(-cqa, kn2, Ca));
                sb[u] = fmaf(c, tb, fmaf(-cqb, kn2, Cb));
            }
            // ---- phase 2: exp + PV accumulate (straight-line) ----
            #pragma unroll
            for (int u = 0; u < CH; u++) {
                float pa = __expf(sa[u]);
                float pb = __expf(sb[u]);
                ls0 += pa; ls1 += pb;
                u64 ppa = pk2(pa, pa), ppb = pk2(pb, pb);
                const ulonglong2* vp = (const ulonglong2*)&sV[(c0 + u) * 8];
                #pragma unroll
                for (int j = 0; j < 8; j++) {
                    ulonglong2 vv = vp[j];
                    acca[2*j]   = ffma2(ppa, vv.x, acca[2*j]);
                    acca[2*j+1] = ffma2(ppa, vv.y, acca[2*j+1]);
                    accb[2*j]   = ffma2(ppb, vv.x, accb[2*j]);
                    accb[2*j+1] = ffma2(ppb, vv.y, accb[2*j+1]);
                }
            }
        }
        __syncthreads();
    }

    // ---- write partials ----
    const int r0 = ((b * L_ + l0) * H_ + h);
    const int r1 = ((b * L_ + l1) * H_ + h);
    g_l[split * NR + r0] = ls0;
    g_l[split * NR + r1] = ls1;
    float4* pa4 = &g_acc[(size_t)(split * NR + r0) * 8];
    float4* pb4 = &g_acc[(size_t)(split * NR + r1) * 8];
    #pragma unroll
    for (int j = 0; j < 8; j++) {
        float2 x = upk2(acca[2*j]), y = upk2(acca[2*j+1]);
        pa4[j] = make_float4(x.x, x.y, y.x, y.y);
        float2 u = upk2(accb[2*j]), v = upk2(accb[2*j+1]);
        pb4[j] = make_float4(u.x, u.y, v.x, v.y);
    }

    // ---- last block of this group merges the splits (plain sums) ----
    const int g = blockIdx.x + (L_ / ROWSPB) * (h + H_ * b);
    __threadfence();
    if (tid == 0) {
        int prev = atomicAdd(&g_cnt[g], 1);
        sLast = (prev == SPLITS - 1);
    }
    __syncthreads();
    if (!sLast) return;
    __threadfence();

    // 64 threads merge 128 rows x 8 float4 chunks = 1024 items.
    #pragma unroll 1
    for (int it = 0; it < (ROWSPB * 8) / THREADS; it++) {
        int item = it * THREADS + tid;
        int rl = item >> 3;
        int jj = item & 7;
        int r  = ((b * L_ + lbase + rl) * H_ + h);
        float denom = 0.f;
        float4 o = make_float4(0.f, 0.f, 0.f, 0.f);
        #pragma unroll
        for (int sp = 0; sp < SPLITS; sp++) {
            denom += g_l[sp * NR + r];
            float4 a = g_acc[(size_t)(sp * NR + r) * 8 + jj];
            o.x += a.x; o.y += a.y; o.z += a.z; o.w += a.w;
        }
        float inv = 1.0f / denom;
        o.x *= inv; o.y *= inv; o.z *= inv; o.w *= inv;
        ((float4*)O)[(size_t)r * 8 + jj] = o;
    }
    if (tid == 0) g_cnt[g] = 0;   // self-reset for next graph replay
}

extern "C" void kernel_launch(void* const* d_in, const int* in_sizes, int n_in,
                              void* d_out, int out_size) {
    const float* Q = (const float*)d_in[0];
    const float* K = (const float*)d_in[1];
    const float* V = (const float*)d_in[2];
    float* O = (float*)d_out;
    (void)in_sizes; (void)n_in; (void)out_size;
    kprep_kernel<<<B_ * H_, 256>>>(K);
    dim3 grid(L_ / ROWSPB, H_, B_ * SPLITS);   // 16 x 8 x 4 = 512 blocks
    geom_attn_fused<<<grid, THREADS>>>(Q, K, V, O);
}